// round 1
// baseline (speedup 1.0000x reference)
#include <cuda_runtime.h>

#define D        256
#define TM       128
#define TN       128
#define KB       32
#define SSTRIDE  132
#define MAX_M    1024
#define MAX_N    100000
#define NBC      10

// -------- device scratch (no allocations allowed) --------
__device__ float              g_xq[MAX_M * D];     // normalized, centered queries
__device__ float              g_nx2[MAX_N];        // ||X_t||^2
__device__ unsigned long long g_min[MAX_M];        // packed (ordered-score | index)

__device__ __forceinline__ unsigned int f2ord(float f) {
    unsigned int u = __float_as_uint(f);
    return (u & 0x80000000u) ? ~u : (u | 0x80000000u);
}

// ---------------------------------------------------------------------------
// 1) xq = x / ||x|| - center       (one block per query, 256 threads = D)
// ---------------------------------------------------------------------------
__global__ void prep_kernel(const float* __restrict__ x,
                            const float* __restrict__ center, int M) {
    int b = blockIdx.x;
    int t = threadIdx.x;
    float v = x[b * D + t];
    float s = v * v;
    __shared__ float red[8];
    #pragma unroll
    for (int o = 16; o > 0; o >>= 1) s += __shfl_xor_sync(0xffffffffu, s, o);
    if ((t & 31) == 0) red[t >> 5] = s;
    __syncthreads();
    if (t < 8) {
        float r = red[t];
        #pragma unroll
        for (int o = 4; o > 0; o >>= 1) r += __shfl_xor_sync(0xffu, r, o);
        if (t == 0) red[0] = r;
    }
    __syncthreads();
    float norm = sqrtf(red[0]);
    g_xq[b * D + t] = v / norm - center[t];
}

// ---------------------------------------------------------------------------
// 2) ||X_t||^2 for every train row   (one warp per row)
// ---------------------------------------------------------------------------
__global__ void norm2_kernel(const float* __restrict__ X, int N) {
    int w    = (blockIdx.x * blockDim.x + threadIdx.x) >> 5;
    int lane = threadIdx.x & 31;
    if (w >= N) return;
    const float4* row = (const float4*)(X + (size_t)w * D);
    float s = 0.f;
    #pragma unroll
    for (int j = 0; j < 2; j++) {
        float4 v = row[lane + 32 * j];
        s += v.x * v.x + v.y * v.y + v.z * v.z + v.w * v.w;
    }
    #pragma unroll
    for (int o = 16; o > 0; o >>= 1) s += __shfl_xor_sync(0xffffffffu, s, o);
    if (lane == 0) g_nx2[w] = s;
}

// ---------------------------------------------------------------------------
// 3) reset argmin scratch (graph replays must be deterministic)
// ---------------------------------------------------------------------------
__global__ void init_kernel(int M) {
    int i = blockIdx.x * blockDim.x + threadIdx.x;
    if (i < M) g_min[i] = ~0ull;
}

// ---------------------------------------------------------------------------
// 4) fused SGEMM + argmin:  score[b,t] = ||X_t||^2 - 2 * <xq_b, X_t>
//    128x128 block tile, 8x8 per thread, K-chunk 32, fp32 exact.
// ---------------------------------------------------------------------------
__global__ __launch_bounds__(256, 2)
void gemm_argmin_kernel(const float* __restrict__ X, int N, int M) {
    __shared__ float As[KB * SSTRIDE];
    __shared__ float Bs[KB * SSTRIDE];
    __shared__ float nx2s[TN];

    int tid = threadIdx.x;
    int tx  = tid & 15;
    int ty  = tid >> 4;
    int m0  = blockIdx.x * TM;   // query tile (8 tiles)
    int n0  = blockIdx.y * TN;   // train tile (782 tiles)

    if (tid < TN) {
        int gn = n0 + tid;
        nx2s[tid] = (gn < N) ? g_nx2[gn] : 0.f;
    }

    float acc[8][8];
    #pragma unroll
    for (int i = 0; i < 8; i++)
        #pragma unroll
        for (int j = 0; j < 8; j++) acc[i][j] = 0.f;

    for (int kc = 0; kc < D; kc += KB) {
        __syncthreads();
        // load A tile (queries), transpose into As[k][m], padded stride
        #pragma unroll
        for (int r = 0; r < 4; r++) {
            int idx = tid + 256 * r;
            int mm  = idx >> 3;
            int k4  = idx & 7;
            int gm  = m0 + mm;
            float4 v = make_float4(0.f, 0.f, 0.f, 0.f);
            if (gm < M) v = *(const float4*)(&g_xq[gm * D + kc + k4 * 4]);
            As[(k4 * 4 + 0) * SSTRIDE + mm] = v.x;
            As[(k4 * 4 + 1) * SSTRIDE + mm] = v.y;
            As[(k4 * 4 + 2) * SSTRIDE + mm] = v.z;
            As[(k4 * 4 + 3) * SSTRIDE + mm] = v.w;
        }
        // load B tile (train rows), transpose into Bs[k][n]
        #pragma unroll
        for (int r = 0; r < 4; r++) {
            int idx = tid + 256 * r;
            int nn  = idx >> 3;
            int k4  = idx & 7;
            int gn  = n0 + nn;
            float4 v = make_float4(0.f, 0.f, 0.f, 0.f);
            if (gn < N) v = *(const float4*)(&X[(size_t)gn * D + kc + k4 * 4]);
            Bs[(k4 * 4 + 0) * SSTRIDE + nn] = v.x;
            Bs[(k4 * 4 + 1) * SSTRIDE + nn] = v.y;
            Bs[(k4 * 4 + 2) * SSTRIDE + nn] = v.z;
            Bs[(k4 * 4 + 3) * SSTRIDE + nn] = v.w;
        }
        __syncthreads();

        #pragma unroll
        for (int kk = 0; kk < KB; kk++) {
            float a[8], b[8];
            *(float4*)&a[0] = *(const float4*)&As[kk * SSTRIDE + ty * 8];
            *(float4*)&a[4] = *(const float4*)&As[kk * SSTRIDE + ty * 8 + 4];
            *(float4*)&b[0] = *(const float4*)&Bs[kk * SSTRIDE + tx * 8];
            *(float4*)&b[4] = *(const float4*)&Bs[kk * SSTRIDE + tx * 8 + 4];
            #pragma unroll
            for (int i = 0; i < 8; i++)
                #pragma unroll
                for (int j = 0; j < 8; j++)
                    acc[i][j] = fmaf(a[i], b[j], acc[i][j]);
        }
    }

    // epilogue: per-row argmin over this block's 128 train cols, merge globally
    #pragma unroll
    for (int i = 0; i < 8; i++) {
        int gm = m0 + ty * 8 + i;
        unsigned long long key = ~0ull;
        #pragma unroll
        for (int j = 0; j < 8; j++) {
            int gn = n0 + tx * 8 + j;
            if (gn < N) {
                float score = nx2s[tx * 8 + j] - 2.f * acc[i][j];
                unsigned long long k =
                    ((unsigned long long)f2ord(score) << 32) | (unsigned int)gn;
                if (k < key) key = k;
            }
        }
        #pragma unroll
        for (int o = 8; o > 0; o >>= 1) {
            unsigned long long other = __shfl_xor_sync(0xffffffffu, key, o);
            if (other < key) key = other;
        }
        if (tx == 0 && gm < M) atomicMin(&g_min[gm], key);
    }
}

// ---------------------------------------------------------------------------
// 5) gather 75 neighbor labels, bincount, conformal p-values, creds
//    one warp per query
// ---------------------------------------------------------------------------
__global__ void finalize_kernel(const int* __restrict__ labels,
                                const int* __restrict__ tni,
                                const int* __restrict__ cali,
                                float* __restrict__ out,
                                int M, int ncali, int Kn) {
    __shared__ int scali[1024];
    __shared__ int wcnt[8][NBC];
    for (int i = threadIdx.x; i < ncali; i += blockDim.x) scali[i] = cali[i];
    int w    = threadIdx.x >> 5;
    int lane = threadIdx.x & 31;
    if (lane < NBC) wcnt[w][lane] = 0;
    __syncthreads();

    int b = blockIdx.x * 8 + w;
    if (b < M) {
        int closest = (int)(g_min[b] & 0xffffffffull);
        for (int e = lane; e < Kn; e += 32) {
            int idx = (e == 0) ? closest : tni[(size_t)closest * (Kn - 1) + (e - 1)];
            int lab = labels[idx];
            atomicAdd(&wcnt[w][lab], 1);
        }
        __syncwarp();
        // lanes 0..9: p-value per class; argmax p == argmin pos, tie -> low class
        int key = 0x7fffffff;
        if (lane < NBC) {
            int v  = Kn - wcnt[w][lane];
            int lo = 0, hi = ncali;
            while (lo < hi) {
                int mid = (lo + hi) >> 1;
                if (scali[mid] < v) lo = mid + 1; else hi = mid;
            }
            key = lo * 16 + lane;
        }
        #pragma unroll
        for (int o = 16; o > 0; o >>= 1)
            key = min(key, __shfl_xor_sync(0xffffffffu, key, o));
        if (lane == 0) {
            int   pred = key & 15;
            int   pos  = key >> 4;
            float pmax = (float)(ncali - pos) / (float)ncali;
            #pragma unroll
            for (int c = 0; c < NBC; c++)
                out[b * NBC + c] = (c == pred) ? pmax : 0.f;
        }
    }
}

// ---------------------------------------------------------------------------
extern "C" void kernel_launch(void* const* d_in, const int* in_sizes, int n_in,
                              void* d_out, int out_size) {
    const float* x      = (const float*)d_in[0];
    const float* X      = (const float*)d_in[1];
    const float* center = (const float*)d_in[2];
    const int*   labels = (const int*)d_in[3];
    const int*   tni    = (const int*)d_in[4];
    const int*   cali   = (const int*)d_in[5];
    float*       out    = (float*)d_out;

    int d     = in_sizes[2];                 // 256
    int M     = in_sizes[0] / d;             // 1024
    int N     = in_sizes[3];                 // 100000
    int ncali = in_sizes[5];                 // 1000
    int Kn    = in_sizes[4] / N + 1;         // 75

    prep_kernel<<<M, 256>>>(x, center, M);
    norm2_kernel<<<(N + 7) / 8, 256>>>(X, N);
    init_kernel<<<(M + 255) / 256, 256>>>(M);

    dim3 grid((M + TM - 1) / TM, (N + TN - 1) / TN);
    gemm_argmin_kernel<<<grid, 256>>>(X, N, M);

    finalize_kernel<<<(M + 7) / 8, 256>>>(labels, tni, cali, out, M, ncali, Kn);
}

// round 2
// speedup vs baseline: 1.0014x; 1.0014x over previous
#include <cuda_runtime.h>

#define D        256
#define TM       128
#define TN       128
#define KB       32
#define SSTRIDE  132
#define MAX_M    1024
#define MAX_N    100000
#define NBC      10

// -------- device scratch (no allocations allowed) --------
__device__ float              g_xq[MAX_M * D];     // normalized, centered queries
__device__ float              g_nx2[MAX_N];        // ||X_t||^2
__device__ unsigned long long g_min[MAX_M];        // packed (ordered-score | index)

__device__ __forceinline__ unsigned int f2ord(float f) {
    unsigned int u = __float_as_uint(f);
    return (u & 0x80000000u) ? ~u : (u | 0x80000000u);
}

// ---------------------------------------------------------------------------
// 1) xq = x / ||x|| - center       (one block per query, 256 threads = D)
// ---------------------------------------------------------------------------
__global__ void prep_kernel(const float* __restrict__ x,
                            const float* __restrict__ center, int M) {
    int b = blockIdx.x;
    int t = threadIdx.x;
    float v = x[b * D + t];
    float s = v * v;
    __shared__ float red[8];
    #pragma unroll
    for (int o = 16; o > 0; o >>= 1) s += __shfl_xor_sync(0xffffffffu, s, o);
    if ((t & 31) == 0) red[t >> 5] = s;
    __syncthreads();
    if (t < 8) {
        float r = red[t];
        #pragma unroll
        for (int o = 4; o > 0; o >>= 1) r += __shfl_xor_sync(0xffu, r, o);
        if (t == 0) red[0] = r;
    }
    __syncthreads();
    float norm = sqrtf(red[0]);
    g_xq[b * D + t] = v / norm - center[t];
}

// ---------------------------------------------------------------------------
// 2) ||X_t||^2 for every train row   (one warp per row)
// ---------------------------------------------------------------------------
__global__ void norm2_kernel(const float* __restrict__ X, int N) {
    int w    = (blockIdx.x * blockDim.x + threadIdx.x) >> 5;
    int lane = threadIdx.x & 31;
    if (w >= N) return;
    const float4* row = (const float4*)(X + (size_t)w * D);
    float s = 0.f;
    #pragma unroll
    for (int j = 0; j < 2; j++) {
        float4 v = row[lane + 32 * j];
        s += v.x * v.x + v.y * v.y + v.z * v.z + v.w * v.w;
    }
    #pragma unroll
    for (int o = 16; o > 0; o >>= 1) s += __shfl_xor_sync(0xffffffffu, s, o);
    if (lane == 0) g_nx2[w] = s;
}

// ---------------------------------------------------------------------------
// 3) reset argmin scratch (graph replays must be deterministic)
// ---------------------------------------------------------------------------
__global__ void init_kernel(int M) {
    int i = blockIdx.x * blockDim.x + threadIdx.x;
    if (i < M) g_min[i] = ~0ull;
}

// ---------------------------------------------------------------------------
// 4) fused SGEMM + argmin:  score[b,t] = ||X_t||^2 - 2 * <xq_b, X_t>
//    128x128 block tile, 8x8 per thread, K-chunk 32, fp32 exact.
// ---------------------------------------------------------------------------
__global__ __launch_bounds__(256, 2)
void gemm_argmin_kernel(const float* __restrict__ X, int N, int M) {
    __shared__ float As[KB * SSTRIDE];
    __shared__ float Bs[KB * SSTRIDE];
    __shared__ float nx2s[TN];

    int tid = threadIdx.x;
    int tx  = tid & 15;
    int ty  = tid >> 4;
    int m0  = blockIdx.x * TM;   // query tile (8 tiles)
    int n0  = blockIdx.y * TN;   // train tile (782 tiles)

    if (tid < TN) {
        int gn = n0 + tid;
        nx2s[tid] = (gn < N) ? g_nx2[gn] : 0.f;
    }

    float acc[8][8];
    #pragma unroll
    for (int i = 0; i < 8; i++)
        #pragma unroll
        for (int j = 0; j < 8; j++) acc[i][j] = 0.f;

    for (int kc = 0; kc < D; kc += KB) {
        __syncthreads();
        // load A tile (queries), transpose into As[k][m], padded stride
        #pragma unroll
        for (int r = 0; r < 4; r++) {
            int idx = tid + 256 * r;
            int mm  = idx >> 3;
            int k4  = idx & 7;
            int gm  = m0 + mm;
            float4 v = make_float4(0.f, 0.f, 0.f, 0.f);
            if (gm < M) v = *(const float4*)(&g_xq[gm * D + kc + k4 * 4]);
            As[(k4 * 4 + 0) * SSTRIDE + mm] = v.x;
            As[(k4 * 4 + 1) * SSTRIDE + mm] = v.y;
            As[(k4 * 4 + 2) * SSTRIDE + mm] = v.z;
            As[(k4 * 4 + 3) * SSTRIDE + mm] = v.w;
        }
        // load B tile (train rows), transpose into Bs[k][n]
        #pragma unroll
        for (int r = 0; r < 4; r++) {
            int idx = tid + 256 * r;
            int nn  = idx >> 3;
            int k4  = idx & 7;
            int gn  = n0 + nn;
            float4 v = make_float4(0.f, 0.f, 0.f, 0.f);
            if (gn < N) v = *(const float4*)(&X[(size_t)gn * D + kc + k4 * 4]);
            Bs[(k4 * 4 + 0) * SSTRIDE + nn] = v.x;
            Bs[(k4 * 4 + 1) * SSTRIDE + nn] = v.y;
            Bs[(k4 * 4 + 2) * SSTRIDE + nn] = v.z;
            Bs[(k4 * 4 + 3) * SSTRIDE + nn] = v.w;
        }
        __syncthreads();

        #pragma unroll
        for (int kk = 0; kk < KB; kk++) {
            float a[8], b[8];
            *(float4*)&a[0] = *(const float4*)&As[kk * SSTRIDE + ty * 8];
            *(float4*)&a[4] = *(const float4*)&As[kk * SSTRIDE + ty * 8 + 4];
            *(float4*)&b[0] = *(const float4*)&Bs[kk * SSTRIDE + tx * 8];
            *(float4*)&b[4] = *(const float4*)&Bs[kk * SSTRIDE + tx * 8 + 4];
            #pragma unroll
            for (int i = 0; i < 8; i++)
                #pragma unroll
                for (int j = 0; j < 8; j++)
                    acc[i][j] = fmaf(a[i], b[j], acc[i][j]);
        }
    }

    // epilogue: per-row argmin over this block's 128 train cols, merge globally
    #pragma unroll
    for (int i = 0; i < 8; i++) {
        int gm = m0 + ty * 8 + i;
        unsigned long long key = ~0ull;
        #pragma unroll
        for (int j = 0; j < 8; j++) {
            int gn = n0 + tx * 8 + j;
            if (gn < N) {
                float score = nx2s[tx * 8 + j] - 2.f * acc[i][j];
                unsigned long long k =
                    ((unsigned long long)f2ord(score) << 32) | (unsigned int)gn;
                if (k < key) key = k;
            }
        }
        #pragma unroll
        for (int o = 8; o > 0; o >>= 1) {
            unsigned long long other = __shfl_xor_sync(0xffffffffu, key, o);
            if (other < key) key = other;
        }
        if (tx == 0 && gm < M) atomicMin(&g_min[gm], key);
    }
}

// ---------------------------------------------------------------------------
// 5) gather 75 neighbor labels, bincount, conformal p-values, creds
//    one warp per query
// ---------------------------------------------------------------------------
__global__ void finalize_kernel(const int* __restrict__ labels,
                                const int* __restrict__ tni,
                                const int* __restrict__ cali,
                                float* __restrict__ out,
                                int M, int ncali, int Kn) {
    __shared__ int scali[1024];
    __shared__ int wcnt[8][NBC];
    for (int i = threadIdx.x; i < ncali; i += blockDim.x) scali[i] = cali[i];
    int w    = threadIdx.x >> 5;
    int lane = threadIdx.x & 31;
    if (lane < NBC) wcnt[w][lane] = 0;
    __syncthreads();

    int b = blockIdx.x * 8 + w;
    if (b < M) {
        int closest = (int)(g_min[b] & 0xffffffffull);
        for (int e = lane; e < Kn; e += 32) {
            int idx = (e == 0) ? closest : tni[(size_t)closest * (Kn - 1) + (e - 1)];
            int lab = labels[idx];
            atomicAdd(&wcnt[w][lab], 1);
        }
        __syncwarp();
        // lanes 0..9: p-value per class; argmax p == argmin pos, tie -> low class
        int key = 0x7fffffff;
        if (lane < NBC) {
            int v  = Kn - wcnt[w][lane];
            int lo = 0, hi = ncali;
            while (lo < hi) {
                int mid = (lo + hi) >> 1;
                if (scali[mid] < v) lo = mid + 1; else hi = mid;
            }
            key = lo * 16 + lane;
        }
        #pragma unroll
        for (int o = 16; o > 0; o >>= 1)
            key = min(key, __shfl_xor_sync(0xffffffffu, key, o));
        if (lane == 0) {
            int   pred = key & 15;
            int   pos  = key >> 4;
            float pmax = (float)(ncali - pos) / (float)ncali;
            #pragma unroll
            for (int c = 0; c < NBC; c++)
                out[b * NBC + c] = (c == pred) ? pmax : 0.f;
        }
    }
}

// ---------------------------------------------------------------------------
extern "C" void kernel_launch(void* const* d_in, const int* in_sizes, int n_in,
                              void* d_out, int out_size) {
    const float* x      = (const float*)d_in[0];
    const float* X      = (const float*)d_in[1];
    const float* center = (const float*)d_in[2];
    const int*   labels = (const int*)d_in[3];
    const int*   tni    = (const int*)d_in[4];
    const int*   cali   = (const int*)d_in[5];
    float*       out    = (float*)d_out;

    int d     = in_sizes[2];                 // 256
    int M     = in_sizes[0] / d;             // 1024
    int N     = in_sizes[3];                 // 100000
    int ncali = in_sizes[5];                 // 1000
    int Kn    = in_sizes[4] / N + 1;         // 75

    prep_kernel<<<M, 256>>>(x, center, M);
    norm2_kernel<<<(N + 7) / 8, 256>>>(X, N);
    init_kernel<<<(M + 255) / 256, 256>>>(M);

    dim3 grid((M + TM - 1) / TM, (N + TN - 1) / TN);
    gemm_argmin_kernel<<<grid, 256>>>(X, N, M);

    finalize_kernel<<<(M + 7) / 8, 256>>>(labels, tni, cali, out, M, ncali, Kn);
}

// round 4
// speedup vs baseline: 2.2935x; 2.2902x over previous
#include <cuda_runtime.h>
#include <cuda_bf16.h>
#include <mma.h>
#include <cstdint>

using namespace nvcuda;

#define D_DIM    256
#define NBC      10
#define MAX_M    1024
#define MAX_N    100000
#define MAX_NP   100096          // padded to whole 128-tiles
#define CAP      2048
#define MARGIN   0.03f
#define KC       64
#define ASTRIDE  72              // bf16 elems per smem row (64 + 8 pad)
#define SSTRIDE  132             // fp32 elems per score row

#define SM_A     0                       // 128 x 72 bf16 = 18432 B
#define SM_B     18432                   // 128 x 72 bf16 = 18432 B
#define SM_SC    36864                   // 128 x 132 f32 = 67584 B
#define SM_NX    (36864 + 67584)         // 128 f32       = 512 B
#define SMEM_BYTES (36864 + 67584 + 512)

__device__ float              g_xq[MAX_M * D_DIM];
__device__ unsigned short     g_qb[MAX_M * D_DIM];
__device__ unsigned short     g_Xb[(size_t)MAX_NP * D_DIM];   // pad rows stay 0
__device__ float              g_nx2[MAX_N];
__device__ unsigned long long g_min[MAX_M];
__device__ int                g_cnum[MAX_M];
__device__ int                g_cand[MAX_M * CAP];

__device__ __forceinline__ unsigned f2ord(float f) {
    unsigned u = __float_as_uint(f);
    return (u & 0x80000000u) ? ~u : (u | 0x80000000u);
}
__device__ __forceinline__ float ord2f(unsigned o) {
    return __uint_as_float((o & 0x80000000u) ? (o ^ 0x80000000u) : ~o);
}

// ---------------------------------------------------------------------------
// 1) queries: normalize, center -> fp32 + bf16
// ---------------------------------------------------------------------------
__global__ void prep_kernel(const float* __restrict__ x,
                            const float* __restrict__ center, int M) {
    int b = blockIdx.x, t = threadIdx.x;
    float v = x[b * D_DIM + t];
    float s = v * v;
    __shared__ float red[8];
    #pragma unroll
    for (int o = 16; o > 0; o >>= 1) s += __shfl_xor_sync(0xffffffffu, s, o);
    if ((t & 31) == 0) red[t >> 5] = s;
    __syncthreads();
    if (t < 8) {
        float r = red[t];
        #pragma unroll
        for (int o = 4; o > 0; o >>= 1) r += __shfl_xor_sync(0xffu, r, o);
        if (t == 0) red[0] = r;
    }
    __syncthreads();
    float val = v / sqrtf(red[0]) - center[t];
    g_xq[b * D_DIM + t] = val;
    g_qb[b * D_DIM + t] = __bfloat16_as_ushort(__float2bfloat16(val));
}

// ---------------------------------------------------------------------------
// 2) X -> bf16 + ||X||^2
// ---------------------------------------------------------------------------
__global__ void convert_kernel(const float* __restrict__ X, int N) {
    int w = (blockIdx.x * blockDim.x + threadIdx.x) >> 5;
    int lane = threadIdx.x & 31;
    if (w >= N) return;
    const float4* row = (const float4*)(X + (size_t)w * D_DIM);
    float4 v0 = row[lane * 2], v1 = row[lane * 2 + 1];
    float s = v0.x*v0.x + v0.y*v0.y + v0.z*v0.z + v0.w*v0.w
            + v1.x*v1.x + v1.y*v1.y + v1.z*v1.z + v1.w*v1.w;
    #pragma unroll
    for (int o = 16; o > 0; o >>= 1) s += __shfl_xor_sync(0xffffffffu, s, o);
    if (lane == 0) g_nx2[w] = s;
    uint4 o4;
    o4.x = __bfloat16_as_ushort(__float2bfloat16(v0.x)) | ((unsigned)__bfloat16_as_ushort(__float2bfloat16(v0.y)) << 16);
    o4.y = __bfloat16_as_ushort(__float2bfloat16(v0.z)) | ((unsigned)__bfloat16_as_ushort(__float2bfloat16(v0.w)) << 16);
    o4.z = __bfloat16_as_ushort(__float2bfloat16(v1.x)) | ((unsigned)__bfloat16_as_ushort(__float2bfloat16(v1.y)) << 16);
    o4.w = __bfloat16_as_ushort(__float2bfloat16(v1.z)) | ((unsigned)__bfloat16_as_ushort(__float2bfloat16(v1.w)) << 16);
    ((uint4*)(g_Xb + (size_t)w * D_DIM))[lane] = o4;
}

__global__ void init_kernel(int M) {
    int i = blockIdx.x * blockDim.x + threadIdx.x;
    if (i < M) { g_min[i] = ~0ull; g_cnum[i] = 0; }
}

// ---------------------------------------------------------------------------
// 3) bf16 HMMA GEMM (128x128x256) + streaming argmin + candidate collection
// ---------------------------------------------------------------------------
__global__ __launch_bounds__(256)
void gemm_kernel(int N, int M) {
    extern __shared__ char sm[];
    __nv_bfloat16* As = (__nv_bfloat16*)(sm + SM_A);
    __nv_bfloat16* Bs = (__nv_bfloat16*)(sm + SM_B);
    float*         Sc = (float*)(sm + SM_SC);
    float*         nxs = (float*)(sm + SM_NX);

    int tid = threadIdx.x;
    int w = tid >> 5;
    int wm = w >> 1, wn = w & 1;
    int m0 = blockIdx.x * 128;
    int n0 = blockIdx.y * 128;

    if (tid < 128) {
        int gn = n0 + tid;
        nxs[tid] = (gn < N) ? g_nx2[gn] : 1e30f;
    }

    wmma::fragment<wmma::accumulator, 16, 16, 16, float> c[2][4];
    #pragma unroll
    for (int i = 0; i < 2; i++)
        #pragma unroll
        for (int j = 0; j < 4; j++)
            wmma::fill_fragment(c[i][j], 0.0f);

    #pragma unroll
    for (int kc = 0; kc < D_DIM; kc += KC) {
        // load A chunk: 128 rows x 64 cols bf16
        #pragma unroll
        for (int r = 0; r < 4; r++) {
            int idx = tid + 256 * r;
            int row = idx >> 3, g = idx & 7;
            int gm = m0 + row;
            uint4 v = make_uint4(0u, 0u, 0u, 0u);
            if (gm < M) v = ((const uint4*)(g_qb + (size_t)gm * D_DIM + kc))[g];
            *(uint4*)(As + row * ASTRIDE + g * 8) = v;
        }
        // load B chunk: 128 rows (train) x 64 cols
        #pragma unroll
        for (int r = 0; r < 4; r++) {
            int idx = tid + 256 * r;
            int row = idx >> 3, g = idx & 7;
            int gn = n0 + row;
            uint4 v = make_uint4(0u, 0u, 0u, 0u);
            if (gn < MAX_NP)   // pad rows of g_Xb are zero
                v = ((const uint4*)(g_Xb + (size_t)gn * D_DIM + kc))[g];
            *(uint4*)(Bs + row * ASTRIDE + g * 8) = v;
        }
        __syncthreads();

        #pragma unroll
        for (int ks = 0; ks < KC / 16; ks++) {
            wmma::fragment<wmma::matrix_a, 16, 16, 16, __nv_bfloat16, wmma::row_major> a[2];
            wmma::fragment<wmma::matrix_b, 16, 16, 16, __nv_bfloat16, wmma::col_major> b[4];
            #pragma unroll
            for (int i = 0; i < 2; i++)
                wmma::load_matrix_sync(a[i], As + (wm * 32 + i * 16) * ASTRIDE + ks * 16, ASTRIDE);
            #pragma unroll
            for (int j = 0; j < 4; j++)
                wmma::load_matrix_sync(b[j], Bs + (wn * 64 + j * 16) * ASTRIDE + ks * 16, ASTRIDE);
            #pragma unroll
            for (int i = 0; i < 2; i++)
                #pragma unroll
                for (int j = 0; j < 4; j++)
                    wmma::mma_sync(c[i][j], a[i], b[j], c[i][j]);
        }
        __syncthreads();
    }

    // store dots to smem scores
    #pragma unroll
    for (int i = 0; i < 2; i++)
        #pragma unroll
        for (int j = 0; j < 4; j++)
            wmma::store_matrix_sync(Sc + (wm * 32 + i * 16) * SSTRIDE + wn * 64 + j * 16,
                                    c[i][j], SSTRIDE, wmma::mem_row_major);
    __syncthreads();

    // epilogue: 2 threads per query row (64 cols each)
    int row  = tid >> 1;
    int half = tid & 1;
    int q    = m0 + row;
    const float* srow = Sc + row * SSTRIDE + half * 64;
    const float* nrow = nxs + half * 64;
    int colb = n0 + half * 64;

    // pass 1: local min
    unsigned long long kmin = ~0ull;
    #pragma unroll
    for (int j4 = 0; j4 < 16; j4++) {
        float4 d = *(const float4*)(srow + j4 * 4);
        float4 nx = *(const float4*)(nrow + j4 * 4);
        float s0 = fmaf(-2.f, d.x, nx.x), s1 = fmaf(-2.f, d.y, nx.y);
        float s2 = fmaf(-2.f, d.z, nx.z), s3 = fmaf(-2.f, d.w, nx.w);
        int gn = colb + j4 * 4;
        if (gn + 0 < N) { unsigned long long k = ((unsigned long long)f2ord(s0) << 32) | (unsigned)(gn + 0); if (k < kmin) kmin = k; }
        if (gn + 1 < N) { unsigned long long k = ((unsigned long long)f2ord(s1) << 32) | (unsigned)(gn + 1); if (k < kmin) kmin = k; }
        if (gn + 2 < N) { unsigned long long k = ((unsigned long long)f2ord(s2) << 32) | (unsigned)(gn + 2); if (k < kmin) kmin = k; }
        if (gn + 3 < N) { unsigned long long k = ((unsigned long long)f2ord(s3) << 32) | (unsigned)(gn + 3); if (k < kmin) kmin = k; }
    }
    unsigned long long other = __shfl_xor_sync(0xffffffffu, kmin, 1);
    if (other < kmin) kmin = other;

    float thr;
    if (half == 0 && q < M) {
        unsigned long long old = atomicMin(&g_min[q], kmin);
        unsigned long long cur = (old < kmin) ? old : kmin;
        thr = ord2f((unsigned)(cur >> 32)) + MARGIN;
    }
    thr = __shfl_sync(0xffffffffu, thr, tid & 30);  // broadcast from even lane

    // pass 2: candidates within margin
    if (q < M) {
        #pragma unroll
        for (int j4 = 0; j4 < 16; j4++) {
            float4 d = *(const float4*)(srow + j4 * 4);
            float4 nx = *(const float4*)(nrow + j4 * 4);
            float s[4] = { fmaf(-2.f, d.x, nx.x), fmaf(-2.f, d.y, nx.y),
                           fmaf(-2.f, d.z, nx.z), fmaf(-2.f, d.w, nx.w) };
            #pragma unroll
            for (int e = 0; e < 4; e++) {
                int gn = colb + j4 * 4 + e;
                if (gn < N && s[e] < thr) {
                    int p = atomicAdd(&g_cnum[q], 1);
                    if (p < CAP) g_cand[q * CAP + p] = gn;
                }
            }
        }
    }
}

// ---------------------------------------------------------------------------
// 4) exact fp32 rescore of candidates
// ---------------------------------------------------------------------------
__global__ void rescore_kernel(const float* __restrict__ X) {
    __shared__ float xq[D_DIM];
    __shared__ unsigned long long wmin[8];
    int q = blockIdx.x;
    int tid = threadIdx.x, w = tid >> 5, lane = tid & 31;
    xq[tid] = g_xq[q * D_DIM + tid];
    int cnum = min(g_cnum[q], CAP);
    __syncthreads();
    unsigned long long key = ~0ull;
    for (int c = w; c < cnum; c += 8) {
        int gn = g_cand[q * CAP + c];
        const float4* row = (const float4*)(X + (size_t)gn * D_DIM);
        const float4* xv = (const float4*)xq;
        float4 v0 = row[lane * 2], v1 = row[lane * 2 + 1];
        float4 a0 = xv[lane * 2], a1 = xv[lane * 2 + 1];
        float dp = v0.x*a0.x + v0.y*a0.y + v0.z*a0.z + v0.w*a0.w
                 + v1.x*a1.x + v1.y*a1.y + v1.z*a1.z + v1.w*a1.w;
        #pragma unroll
        for (int o = 16; o > 0; o >>= 1) dp += __shfl_xor_sync(0xffffffffu, dp, o);
        float s = g_nx2[gn] - 2.f * dp;
        unsigned long long k = ((unsigned long long)f2ord(s) << 32) | (unsigned)gn;
        if (k < key) key = k;
    }
    if (lane == 0) wmin[w] = key;
    __syncthreads();
    if (tid == 0) {
        unsigned long long best = wmin[0];
        #pragma unroll
        for (int i = 1; i < 8; i++) if (wmin[i] < best) best = wmin[i];
        g_min[q] = best;
    }
}

// ---------------------------------------------------------------------------
// 5) labels gather + conformal p-values + creds
// ---------------------------------------------------------------------------
__global__ void finalize_kernel(const int* __restrict__ labels,
                                const int* __restrict__ tni,
                                const int* __restrict__ cali,
                                float* __restrict__ out,
                                int M, int ncali, int Kn) {
    __shared__ int scali[1024];
    __shared__ int wcnt[8][NBC];
    for (int i = threadIdx.x; i < ncali; i += blockDim.x) scali[i] = cali[i];
    int w = threadIdx.x >> 5, lane = threadIdx.x & 31;
    if (lane < NBC) wcnt[w][lane] = 0;
    __syncthreads();
    int b = blockIdx.x * 8 + w;
    if (b < M) {
        int closest = (int)(g_min[b] & 0xffffffffull);
        for (int e = lane; e < Kn; e += 32) {
            int idx = (e == 0) ? closest : tni[(size_t)closest * (Kn - 1) + (e - 1)];
            atomicAdd(&wcnt[w][labels[idx]], 1);
        }
        __syncwarp();
        int key = 0x7fffffff;
        if (lane < NBC) {
            int v = Kn - wcnt[w][lane];
            int lo = 0, hi = ncali;
            while (lo < hi) {
                int mid = (lo + hi) >> 1;
                if (scali[mid] < v) lo = mid + 1; else hi = mid;
            }
            key = lo * 16 + lane;
        }
        #pragma unroll
        for (int o = 16; o > 0; o >>= 1)
            key = min(key, __shfl_xor_sync(0xffffffffu, key, o));
        if (lane == 0) {
            int pred = key & 15, pos = key >> 4;
            float pmax = (float)(ncali - pos) / (float)ncali;
            #pragma unroll
            for (int c = 0; c < NBC; c++)
                out[b * NBC + c] = (c == pred) ? pmax : 0.f;
        }
    }
}

// ---------------------------------------------------------------------------
extern "C" void kernel_launch(void* const* d_in, const int* in_sizes, int n_in,
                              void* d_out, int out_size) {
    const float* x      = (const float*)d_in[0];
    const float* X      = (const float*)d_in[1];
    const float* center = (const float*)d_in[2];
    const int*   labels = (const int*)d_in[3];
    const int*   tni    = (const int*)d_in[4];
    const int*   cali   = (const int*)d_in[5];
    float*       out    = (float*)d_out;

    int d     = in_sizes[2];
    int M     = in_sizes[0] / d;
    int N     = in_sizes[3];
    int ncali = in_sizes[5];
    int Kn    = in_sizes[4] / N + 1;

    cudaFuncSetAttribute(gemm_kernel, cudaFuncAttributeMaxDynamicSharedMemorySize, SMEM_BYTES);

    prep_kernel<<<M, 256>>>(x, center, M);
    convert_kernel<<<(N + 7) / 8, 256>>>(X, N);
    init_kernel<<<(M + 255) / 256, 256>>>(M);

    dim3 grid((M + 127) / 128, (N + 127) / 128);
    gemm_kernel<<<grid, 256, SMEM_BYTES>>>(N, M);

    rescore_kernel<<<M, 256>>>(X);
    finalize_kernel<<<(M + 7) / 8, 256>>>(labels, tni, cali, out, M, ncali, Kn);
}

// round 5
// speedup vs baseline: 5.1375x; 2.2400x over previous
#include <cuda_runtime.h>
#include <cuda_bf16.h>
#include <cstdint>

#define D_DIM    256
#define NBC      10
#define MAX_M    1024
#define MAX_N    100000
#define MAX_NP   100096
#define CAP      2048
#define MARGIN   0.03f
#define KC       64
#define ASTRIDE  72      // bf16 elems per smem row (64 + 8 pad)

#define SM_A0    0
#define SM_A1    18432
#define SM_B0    36864
#define SM_B1    55296
#define SM_NX    73728
#define SMEM_BYTES 74240

__device__ float              g_xq[MAX_M * D_DIM];
__device__ unsigned short     g_qb[MAX_M * D_DIM];
__device__ unsigned short     g_Xb[(size_t)MAX_NP * D_DIM];   // pad rows stay 0
__device__ float              g_nx2[MAX_N];
__device__ unsigned long long g_min[MAX_M];
__device__ int                g_cnum[MAX_M];
__device__ int                g_cand[MAX_M * CAP];

__device__ __forceinline__ unsigned f2ord(float f) {
    unsigned u = __float_as_uint(f);
    return (u & 0x80000000u) ? ~u : (u | 0x80000000u);
}
__device__ __forceinline__ float ord2f(unsigned o) {
    return __uint_as_float((o & 0x80000000u) ? (o ^ 0x80000000u) : ~o);
}
__device__ __forceinline__ unsigned smem_u32(const void* p) {
    unsigned a;
    asm("{ .reg .u64 t; cvta.to.shared.u64 t, %1; cvt.u32.u64 %0, t; }" : "=r"(a) : "l"(p));
    return a;
}
__device__ __forceinline__ void cp16(unsigned dst, const void* src) {
    asm volatile("cp.async.cg.shared.global [%0], [%1], 16;" :: "r"(dst), "l"(src));
}
#define CP_COMMIT() asm volatile("cp.async.commit_group;" ::: "memory")
#define CP_WAIT(n)  asm volatile("cp.async.wait_group %0;" :: "n"(n) : "memory")

__device__ __forceinline__ void ldsm_x4(unsigned& r0, unsigned& r1, unsigned& r2, unsigned& r3, unsigned addr) {
    asm volatile("ldmatrix.sync.aligned.m8n8.x4.shared.b16 {%0,%1,%2,%3}, [%4];"
        : "=r"(r0), "=r"(r1), "=r"(r2), "=r"(r3) : "r"(addr));
}
__device__ __forceinline__ void ldsm_x2(unsigned& r0, unsigned& r1, unsigned addr) {
    asm volatile("ldmatrix.sync.aligned.m8n8.x2.shared.b16 {%0,%1}, [%2];"
        : "=r"(r0), "=r"(r1) : "r"(addr));
}
__device__ __forceinline__ void mma16816(float* c, const unsigned* a, const unsigned* b) {
    asm volatile(
        "mma.sync.aligned.m16n8k16.row.col.f32.bf16.bf16.f32 "
        "{%0,%1,%2,%3}, {%4,%5,%6,%7}, {%8,%9}, {%0,%1,%2,%3};"
        : "+f"(c[0]), "+f"(c[1]), "+f"(c[2]), "+f"(c[3])
        : "r"(a[0]), "r"(a[1]), "r"(a[2]), "r"(a[3]), "r"(b[0]), "r"(b[1]));
}

// ---------------------------------------------------------------------------
__global__ void prep_kernel(const float* __restrict__ x,
                            const float* __restrict__ center, int M) {
    int b = blockIdx.x, t = threadIdx.x;
    float v = x[b * D_DIM + t];
    float s = v * v;
    __shared__ float red[8];
    #pragma unroll
    for (int o = 16; o > 0; o >>= 1) s += __shfl_xor_sync(0xffffffffu, s, o);
    if ((t & 31) == 0) red[t >> 5] = s;
    __syncthreads();
    if (t < 8) {
        float r = red[t];
        #pragma unroll
        for (int o = 4; o > 0; o >>= 1) r += __shfl_xor_sync(0xffu, r, o);
        if (t == 0) red[0] = r;
    }
    __syncthreads();
    float val = v / sqrtf(red[0]) - center[t];
    g_xq[b * D_DIM + t] = val;
    g_qb[b * D_DIM + t] = __bfloat16_as_ushort(__float2bfloat16(val));
}

__global__ void convert_kernel(const float* __restrict__ X, int N) {
    int w = (blockIdx.x * blockDim.x + threadIdx.x) >> 5;
    int lane = threadIdx.x & 31;
    if (w >= N) return;
    const float4* row = (const float4*)(X + (size_t)w * D_DIM);
    float4 v0 = row[lane * 2], v1 = row[lane * 2 + 1];
    float s = v0.x*v0.x + v0.y*v0.y + v0.z*v0.z + v0.w*v0.w
            + v1.x*v1.x + v1.y*v1.y + v1.z*v1.z + v1.w*v1.w;
    #pragma unroll
    for (int o = 16; o > 0; o >>= 1) s += __shfl_xor_sync(0xffffffffu, s, o);
    if (lane == 0) g_nx2[w] = s;
    uint4 o4;
    o4.x = __bfloat16_as_ushort(__float2bfloat16(v0.x)) | ((unsigned)__bfloat16_as_ushort(__float2bfloat16(v0.y)) << 16);
    o4.y = __bfloat16_as_ushort(__float2bfloat16(v0.z)) | ((unsigned)__bfloat16_as_ushort(__float2bfloat16(v0.w)) << 16);
    o4.z = __bfloat16_as_ushort(__float2bfloat16(v1.x)) | ((unsigned)__bfloat16_as_ushort(__float2bfloat16(v1.y)) << 16);
    o4.w = __bfloat16_as_ushort(__float2bfloat16(v1.z)) | ((unsigned)__bfloat16_as_ushort(__float2bfloat16(v1.w)) << 16);
    ((uint4*)(g_Xb + (size_t)w * D_DIM))[lane] = o4;
}

__global__ void init_kernel(int M) {
    int i = blockIdx.x * blockDim.x + threadIdx.x;
    if (i < M) { g_min[i] = ~0ull; g_cnum[i] = 0; }
}

// ---------------------------------------------------------------------------
// bf16 mma.sync GEMM (128x128x256), reg-resident epilogue, cp.async pipeline
// ---------------------------------------------------------------------------
__device__ __forceinline__ void load_chunk(unsigned Au, unsigned Bu,
                                           int m0, int rowbase, int kc,
                                           int tid, int M) {
    #pragma unroll
    for (int r = 0; r < 4; r++) {
        int idx = tid + 256 * r;
        int row = idx >> 3, g = idx & 7;
        int gm = min(m0 + row, M - 1);
        cp16(Au + (row * ASTRIDE + g * 8) * 2, g_qb + (size_t)gm * D_DIM + kc + g * 8);
        int gn = rowbase + row;   // always < MAX_NP (g_Xb zero-padded)
        cp16(Bu + (row * ASTRIDE + g * 8) * 2, g_Xb + (size_t)gn * D_DIM + kc + g * 8);
    }
}

__global__ __launch_bounds__(256, 2)
void gemm_kernel(int N, int M) {
    extern __shared__ char sm[];
    float* nxs = (float*)(sm + SM_NX);
    unsigned smu = smem_u32(sm);

    int tid = threadIdx.x;
    int w = tid >> 5, lane = tid & 31;
    int wm = w >> 1, wn = w & 1;
    int m0 = blockIdx.x * 128;
    int n0 = blockIdx.y * 128;

    if (tid < 128) {
        int gn = n0 + tid;
        nxs[tid] = (gn < N) ? g_nx2[gn] : 1e30f;
    }

    float c[2][8][4];
    #pragma unroll
    for (int mi = 0; mi < 2; mi++)
        #pragma unroll
        for (int ni = 0; ni < 8; ni++)
            #pragma unroll
            for (int e = 0; e < 4; e++) c[mi][ni][e] = 0.f;

    unsigned abuf[2] = { smu + SM_A0, smu + SM_A1 };
    unsigned bbuf[2] = { smu + SM_B0, smu + SM_B1 };

    load_chunk(abuf[0], bbuf[0], m0, n0, 0, tid, M);
    CP_COMMIT();

    int l = lane & 15;
    #pragma unroll
    for (int kc = 0; kc < 4; kc++) {
        int buf = kc & 1;
        if (kc < 3) {
            load_chunk(abuf[buf ^ 1], bbuf[buf ^ 1], m0, n0, (kc + 1) * KC, tid, M);
            CP_COMMIT();
            CP_WAIT(1);
        } else {
            CP_WAIT(0);
        }
        __syncthreads();

        unsigned Au = abuf[buf], Bu = bbuf[buf];
        #pragma unroll
        for (int ks = 0; ks < 4; ks++) {
            unsigned a[2][4];
            #pragma unroll
            for (int mi = 0; mi < 2; mi++)
                ldsm_x4(a[mi][0], a[mi][1], a[mi][2], a[mi][3],
                        Au + (((wm * 32 + mi * 16 + l) * ASTRIDE) + ks * 16 + (lane >> 4) * 8) * 2);
            unsigned b[8][2];
            #pragma unroll
            for (int ni = 0; ni < 8; ni++)
                ldsm_x2(b[ni][0], b[ni][1],
                        Bu + (((wn * 64 + ni * 8 + (l & 7)) * ASTRIDE) + ks * 16 + ((l >> 3) & 1) * 8) * 2);
            #pragma unroll
            for (int mi = 0; mi < 2; mi++)
                #pragma unroll
                for (int ni = 0; ni < 8; ni++)
                    mma16816(c[mi][ni], a[mi], b[ni]);
        }
        __syncthreads();
    }

    // ---- register epilogue: per-row argmin + margin candidates ----
    int r = lane >> 2, qp = lane & 3;
    #pragma unroll
    for (int mi = 0; mi < 2; mi++) {
        #pragma unroll
        for (int h = 0; h < 2; h++) {
            int lrow = wm * 32 + mi * 16 + h * 8 + r;
            int q = m0 + lrow;
            unsigned long long kmin = ~0ull;
            #pragma unroll
            for (int ni = 0; ni < 8; ni++) {
                int lc = wn * 64 + ni * 8 + 2 * qp;
                float s0 = fmaf(-2.f, c[mi][ni][h * 2 + 0], nxs[lc]);
                float s1 = fmaf(-2.f, c[mi][ni][h * 2 + 1], nxs[lc + 1]);
                unsigned long long k0 = ((unsigned long long)f2ord(s0) << 32) | (unsigned)(n0 + lc);
                unsigned long long k1 = ((unsigned long long)f2ord(s1) << 32) | (unsigned)(n0 + lc + 1);
                if (k0 < kmin) kmin = k0;
                if (k1 < kmin) kmin = k1;
            }
            unsigned long long o1 = __shfl_xor_sync(0xffffffffu, kmin, 1);
            if (o1 < kmin) kmin = o1;
            unsigned long long o2 = __shfl_xor_sync(0xffffffffu, kmin, 2);
            if (o2 < kmin) kmin = o2;

            float thr = 0.f;
            if (qp == 0 && q < M) {
                unsigned long long old = atomicMin(&g_min[q], kmin);
                unsigned long long cur = (old < kmin) ? old : kmin;
                thr = ord2f((unsigned)(cur >> 32)) + MARGIN;
            }
            thr = __shfl_sync(0xffffffffu, thr, lane & ~3);

            if (q < M) {
                #pragma unroll
                for (int ni = 0; ni < 8; ni++) {
                    int lc = wn * 64 + ni * 8 + 2 * qp;
                    float s0 = fmaf(-2.f, c[mi][ni][h * 2 + 0], nxs[lc]);
                    float s1 = fmaf(-2.f, c[mi][ni][h * 2 + 1], nxs[lc + 1]);
                    if (s0 < thr) {
                        int p = atomicAdd(&g_cnum[q], 1);
                        if (p < CAP) g_cand[q * CAP + p] = n0 + lc;
                    }
                    if (s1 < thr) {
                        int p = atomicAdd(&g_cnum[q], 1);
                        if (p < CAP) g_cand[q * CAP + p] = n0 + lc + 1;
                    }
                }
            }
        }
    }
}

// ---------------------------------------------------------------------------
__global__ void rescore_kernel(const float* __restrict__ X) {
    __shared__ float xq[D_DIM];
    __shared__ unsigned long long wmin[8];
    int q = blockIdx.x;
    int tid = threadIdx.x, w = tid >> 5, lane = tid & 31;
    xq[tid] = g_xq[q * D_DIM + tid];
    int cnum = min(g_cnum[q], CAP);
    __syncthreads();
    unsigned long long key = ~0ull;
    for (int c = w; c < cnum; c += 8) {
        int gn = g_cand[q * CAP + c];
        const float4* row = (const float4*)(X + (size_t)gn * D_DIM);
        const float4* xv = (const float4*)xq;
        float4 v0 = row[lane * 2], v1 = row[lane * 2 + 1];
        float4 a0 = xv[lane * 2], a1 = xv[lane * 2 + 1];
        float dp = v0.x*a0.x + v0.y*a0.y + v0.z*a0.z + v0.w*a0.w
                 + v1.x*a1.x + v1.y*a1.y + v1.z*a1.z + v1.w*a1.w;
        #pragma unroll
        for (int o = 16; o > 0; o >>= 1) dp += __shfl_xor_sync(0xffffffffu, dp, o);
        float s = g_nx2[gn] - 2.f * dp;
        unsigned long long k = ((unsigned long long)f2ord(s) << 32) | (unsigned)gn;
        if (k < key) key = k;
    }
    if (lane == 0) wmin[w] = key;
    __syncthreads();
    if (tid == 0) {
        unsigned long long best = wmin[0];
        #pragma unroll
        for (int i = 1; i < 8; i++) if (wmin[i] < best) best = wmin[i];
        g_min[q] = best;
    }
}

// ---------------------------------------------------------------------------
__global__ void finalize_kernel(const int* __restrict__ labels,
                                const int* __restrict__ tni,
                                const int* __restrict__ cali,
                                float* __restrict__ out,
                                int M, int ncali, int Kn) {
    __shared__ int scali[1024];
    __shared__ int wcnt[8][NBC];
    for (int i = threadIdx.x; i < ncali; i += blockDim.x) scali[i] = cali[i];
    int w = threadIdx.x >> 5, lane = threadIdx.x & 31;
    if (lane < NBC) wcnt[w][lane] = 0;
    __syncthreads();
    int b = blockIdx.x * 8 + w;
    if (b < M) {
        int closest = (int)(g_min[b] & 0xffffffffull);
        for (int e = lane; e < Kn; e += 32) {
            int idx = (e == 0) ? closest : tni[(size_t)closest * (Kn - 1) + (e - 1)];
            atomicAdd(&wcnt[w][labels[idx]], 1);
        }
        __syncwarp();
        int key = 0x7fffffff;
        if (lane < NBC) {
            int v = Kn - wcnt[w][lane];
            int lo = 0, hi = ncali;
            while (lo < hi) {
                int mid = (lo + hi) >> 1;
                if (scali[mid] < v) lo = mid + 1; else hi = mid;
            }
            key = lo * 16 + lane;
        }
        #pragma unroll
        for (int o = 16; o > 0; o >>= 1)
            key = min(key, __shfl_xor_sync(0xffffffffu, key, o));
        if (lane == 0) {
            int pred = key & 15, pos = key >> 4;
            float pmax = (float)(ncali - pos) / (float)ncali;
            #pragma unroll
            for (int c = 0; c < NBC; c++)
                out[b * NBC + c] = (c == pred) ? pmax : 0.f;
        }
    }
}

// ---------------------------------------------------------------------------
extern "C" void kernel_launch(void* const* d_in, const int* in_sizes, int n_in,
                              void* d_out, int out_size) {
    const float* x      = (const float*)d_in[0];
    const float* X      = (const float*)d_in[1];
    const float* center = (const float*)d_in[2];
    const int*   labels = (const int*)d_in[3];
    const int*   tni    = (const int*)d_in[4];
    const int*   cali   = (const int*)d_in[5];
    float*       out    = (float*)d_out;

    int d     = in_sizes[2];
    int M     = in_sizes[0] / d;
    int N     = in_sizes[3];
    int ncali = in_sizes[5];
    int Kn    = in_sizes[4] / N + 1;

    cudaFuncSetAttribute(gemm_kernel, cudaFuncAttributeMaxDynamicSharedMemorySize, SMEM_BYTES);

    prep_kernel<<<M, 256>>>(x, center, M);
    convert_kernel<<<(N + 7) / 8, 256>>>(X, N);
    init_kernel<<<(M + 255) / 256, 256>>>(M);

    dim3 grid((M + 127) / 128, (N + 127) / 128);
    gemm_kernel<<<grid, 256, SMEM_BYTES>>>(N, M);

    rescore_kernel<<<M, 256>>>(X);
    finalize_kernel<<<(M + 7) / 8, 256>>>(labels, tni, cali, out, M, ncali, Kn);
}

// round 6
// speedup vs baseline: 5.2582x; 1.0235x over previous
#include <cuda_runtime.h>
#include <cuda_bf16.h>
#include <cstdint>

#define D_DIM    256
#define NBC      10
#define MAX_M    1024
#define MAX_N    100000
#define MAX_NP   100096
#define CAP      2048
#define MARGIN   0.03f
#define KC       64
#define ASTRIDE  72      // bf16 elems per smem row (64 + 8 pad)

#define STAGE_BYTES 36864          // A chunk (18432) + B chunk (18432)
#define SM_NX    (3 * STAGE_BYTES) // 110592
#define SMEM_BYTES (SM_NX + 512)

__device__ float              g_xq[MAX_M * D_DIM];
__device__ unsigned short     g_qb[MAX_M * D_DIM];
__device__ unsigned short     g_Xb[(size_t)MAX_NP * D_DIM];   // pad rows stay 0
__device__ float              g_nx2[MAX_N];
__device__ unsigned long long g_min[MAX_M];
__device__ int                g_cnum[MAX_M];
__device__ int                g_cand[MAX_M * CAP];

__device__ __forceinline__ unsigned f2ord(float f) {
    unsigned u = __float_as_uint(f);
    return (u & 0x80000000u) ? ~u : (u | 0x80000000u);
}
__device__ __forceinline__ float ord2f(unsigned o) {
    return __uint_as_float((o & 0x80000000u) ? (o ^ 0x80000000u) : ~o);
}
__device__ __forceinline__ unsigned smem_u32(const void* p) {
    unsigned a;
    asm("{ .reg .u64 t; cvta.to.shared.u64 t, %1; cvt.u32.u64 %0, t; }" : "=r"(a) : "l"(p));
    return a;
}
__device__ __forceinline__ void cp16(unsigned dst, const void* src) {
    asm volatile("cp.async.cg.shared.global [%0], [%1], 16;" :: "r"(dst), "l"(src));
}
#define CP_COMMIT() asm volatile("cp.async.commit_group;" ::: "memory")
#define CP_WAIT(n)  asm volatile("cp.async.wait_group %0;" :: "n"(n) : "memory")

__device__ __forceinline__ void ldsm_x4(unsigned& r0, unsigned& r1, unsigned& r2, unsigned& r3, unsigned addr) {
    asm volatile("ldmatrix.sync.aligned.m8n8.x4.shared.b16 {%0,%1,%2,%3}, [%4];"
        : "=r"(r0), "=r"(r1), "=r"(r2), "=r"(r3) : "r"(addr));
}
__device__ __forceinline__ void mma16816(float* c, const unsigned* a, unsigned b0, unsigned b1) {
    asm volatile(
        "mma.sync.aligned.m16n8k16.row.col.f32.bf16.bf16.f32 "
        "{%0,%1,%2,%3}, {%4,%5,%6,%7}, {%8,%9}, {%0,%1,%2,%3};"
        : "+f"(c[0]), "+f"(c[1]), "+f"(c[2]), "+f"(c[3])
        : "r"(a[0]), "r"(a[1]), "r"(a[2]), "r"(a[3]), "r"(b0), "r"(b1));
}

// ---------------------------------------------------------------------------
__global__ void prep_kernel(const float* __restrict__ x,
                            const float* __restrict__ center, int M) {
    int b = blockIdx.x, t = threadIdx.x;
    float v = x[b * D_DIM + t];
    float s = v * v;
    __shared__ float red[8];
    #pragma unroll
    for (int o = 16; o > 0; o >>= 1) s += __shfl_xor_sync(0xffffffffu, s, o);
    if ((t & 31) == 0) red[t >> 5] = s;
    __syncthreads();
    if (t < 8) {
        float r = red[t];
        #pragma unroll
        for (int o = 4; o > 0; o >>= 1) r += __shfl_xor_sync(0xffu, r, o);
        if (t == 0) red[0] = r;
    }
    __syncthreads();
    float val = v / sqrtf(red[0]) - center[t];
    g_xq[b * D_DIM + t] = val;
    g_qb[b * D_DIM + t] = __bfloat16_as_ushort(__float2bfloat16(val));
}

__global__ void convert_kernel(const float* __restrict__ X, int N) {
    int w = (blockIdx.x * blockDim.x + threadIdx.x) >> 5;
    int lane = threadIdx.x & 31;
    if (w >= N) return;
    const float4* row = (const float4*)(X + (size_t)w * D_DIM);
    float4 v0 = row[lane * 2], v1 = row[lane * 2 + 1];
    float s = v0.x*v0.x + v0.y*v0.y + v0.z*v0.z + v0.w*v0.w
            + v1.x*v1.x + v1.y*v1.y + v1.z*v1.z + v1.w*v1.w;
    #pragma unroll
    for (int o = 16; o > 0; o >>= 1) s += __shfl_xor_sync(0xffffffffu, s, o);
    if (lane == 0) g_nx2[w] = s;
    uint4 o4;
    o4.x = __bfloat16_as_ushort(__float2bfloat16(v0.x)) | ((unsigned)__bfloat16_as_ushort(__float2bfloat16(v0.y)) << 16);
    o4.y = __bfloat16_as_ushort(__float2bfloat16(v0.z)) | ((unsigned)__bfloat16_as_ushort(__float2bfloat16(v0.w)) << 16);
    o4.z = __bfloat16_as_ushort(__float2bfloat16(v1.x)) | ((unsigned)__bfloat16_as_ushort(__float2bfloat16(v1.y)) << 16);
    o4.w = __bfloat16_as_ushort(__float2bfloat16(v1.z)) | ((unsigned)__bfloat16_as_ushort(__float2bfloat16(v1.w)) << 16);
    ((uint4*)(g_Xb + (size_t)w * D_DIM))[lane] = o4;
}

__global__ void init_kernel(int M) {
    int i = blockIdx.x * blockDim.x + threadIdx.x;
    if (i < M) { g_min[i] = ~0ull; g_cnum[i] = 0; }
}

// ---------------------------------------------------------------------------
// bf16 mma.sync GEMM (128x128x256), 3-stage cp.async pipeline,
// ldmatrix.x4 everywhere, reg-resident argmin/margin epilogue
// ---------------------------------------------------------------------------
__device__ __forceinline__ void load_chunk(unsigned stage, int m0, int n0,
                                           int kc, int tid) {
    #pragma unroll
    for (int r = 0; r < 4; r++) {
        int idx = tid + 256 * r;
        int row = idx >> 3, g = idx & 7;
        cp16(stage + (row * ASTRIDE + g * 8) * 2,
             g_qb + (size_t)(m0 + row) * D_DIM + kc + g * 8);
        cp16(stage + 18432 + (row * ASTRIDE + g * 8) * 2,
             g_Xb + (size_t)(n0 + row) * D_DIM + kc + g * 8);
    }
}

__global__ __launch_bounds__(256, 2)
void gemm_kernel(int N, int M) {
    extern __shared__ char sm[];
    float* nxs = (float*)(sm + SM_NX);
    unsigned smu = smem_u32(sm);

    int tid = threadIdx.x;
    int w = tid >> 5, lane = tid & 31;
    int wm = w >> 1, wn = w & 1;
    int m0 = blockIdx.x * 128;
    int n0 = blockIdx.y * 128;

    if (tid < 128) {
        int gn = n0 + tid;
        nxs[tid] = (gn < N) ? g_nx2[gn] : 1e30f;
    }

    float c[2][8][4];
    #pragma unroll
    for (int mi = 0; mi < 2; mi++)
        #pragma unroll
        for (int ni = 0; ni < 8; ni++)
            #pragma unroll
            for (int e = 0; e < 4; e++) c[mi][ni][e] = 0.f;

    // hoisted lane-dependent ldmatrix byte offsets (within a stage)
    unsigned aoff = (unsigned)(((wm * 32 + (lane & 15)) * ASTRIDE + (lane >> 4) * 8) * 2);
    int bg = lane >> 3, br = lane & 7;
    unsigned boff = (unsigned)(18432 + ((wn * 64 + (bg >> 1) * 8 + br) * ASTRIDE + (bg & 1) * 8) * 2);

    load_chunk(smu, m0, n0, 0, tid);
    CP_COMMIT();
    load_chunk(smu + STAGE_BYTES, m0, n0, KC, tid);
    CP_COMMIT();

    #pragma unroll
    for (int kc = 0; kc < 4; kc++) {
        if (kc < 3) { CP_WAIT(1); } else { CP_WAIT(0); }
        __syncthreads();
        if (kc + 2 < 4) {
            load_chunk(smu + ((kc + 2) % 3) * STAGE_BYTES, m0, n0, (kc + 2) * KC, tid);
            CP_COMMIT();
        }
        unsigned stage = smu + (kc % 3) * STAGE_BYTES;
        unsigned Au = stage + aoff;
        unsigned Bu = stage + boff;
        #pragma unroll
        for (int ks = 0; ks < 4; ks++) {
            unsigned a[2][4];
            #pragma unroll
            for (int mi = 0; mi < 2; mi++)
                ldsm_x4(a[mi][0], a[mi][1], a[mi][2], a[mi][3],
                        Au + mi * (16 * ASTRIDE * 2) + ks * 32);
            unsigned b[4][4];
            #pragma unroll
            for (int p = 0; p < 4; p++)
                ldsm_x4(b[p][0], b[p][1], b[p][2], b[p][3],
                        Bu + p * (16 * ASTRIDE * 2) + ks * 32);
            #pragma unroll
            for (int mi = 0; mi < 2; mi++)
                #pragma unroll
                for (int p = 0; p < 4; p++) {
                    mma16816(c[mi][2 * p + 0], a[mi], b[p][0], b[p][1]);
                    mma16816(c[mi][2 * p + 1], a[mi], b[p][2], b[p][3]);
                }
        }
    }

    // ---- register epilogue: per-row argmin + margin candidates ----
    int r = lane >> 2, qp = lane & 3;
    #pragma unroll
    for (int mi = 0; mi < 2; mi++) {
        #pragma unroll
        for (int h = 0; h < 2; h++) {
            int lrow = wm * 32 + mi * 16 + h * 8 + r;
            int q = m0 + lrow;
            unsigned long long kmin = ~0ull;
            #pragma unroll
            for (int ni = 0; ni < 8; ni++) {
                int lc = wn * 64 + ni * 8 + 2 * qp;
                float s0 = fmaf(-2.f, c[mi][ni][h * 2 + 0], nxs[lc]);
                float s1 = fmaf(-2.f, c[mi][ni][h * 2 + 1], nxs[lc + 1]);
                unsigned long long k0 = ((unsigned long long)f2ord(s0) << 32) | (unsigned)(n0 + lc);
                unsigned long long k1 = ((unsigned long long)f2ord(s1) << 32) | (unsigned)(n0 + lc + 1);
                if (k0 < kmin) kmin = k0;
                if (k1 < kmin) kmin = k1;
            }
            unsigned long long o1 = __shfl_xor_sync(0xffffffffu, kmin, 1);
            if (o1 < kmin) kmin = o1;
            unsigned long long o2 = __shfl_xor_sync(0xffffffffu, kmin, 2);
            if (o2 < kmin) kmin = o2;

            float thr = 0.f;
            if (qp == 0 && q < M) {
                unsigned long long old = atomicMin(&g_min[q], kmin);
                unsigned long long cur = (old < kmin) ? old : kmin;
                thr = ord2f((unsigned)(cur >> 32)) + MARGIN;
            }
            thr = __shfl_sync(0xffffffffu, thr, lane & ~3);

            if (q < M) {
                #pragma unroll
                for (int ni = 0; ni < 8; ni++) {
                    int lc = wn * 64 + ni * 8 + 2 * qp;
                    float s0 = fmaf(-2.f, c[mi][ni][h * 2 + 0], nxs[lc]);
                    float s1 = fmaf(-2.f, c[mi][ni][h * 2 + 1], nxs[lc + 1]);
                    if (s0 < thr) {
                        int p = atomicAdd(&g_cnum[q], 1);
                        if (p < CAP) g_cand[q * CAP + p] = n0 + lc;
                    }
                    if (s1 < thr) {
                        int p = atomicAdd(&g_cnum[q], 1);
                        if (p < CAP) g_cand[q * CAP + p] = n0 + lc + 1;
                    }
                }
            }
        }
    }
}

// ---------------------------------------------------------------------------
__global__ void rescore_kernel(const float* __restrict__ X) {
    __shared__ float xq[D_DIM];
    __shared__ unsigned long long wmin[8];
    int q = blockIdx.x;
    int tid = threadIdx.x, w = tid >> 5, lane = tid & 31;
    xq[tid] = g_xq[q * D_DIM + tid];
    int cnum = min(g_cnum[q], CAP);
    __syncthreads();
    unsigned long long key = ~0ull;
    for (int c = w; c < cnum; c += 8) {
        int gn = g_cand[q * CAP + c];
        const float4* row = (const float4*)(X + (size_t)gn * D_DIM);
        const float4* xv = (const float4*)xq;
        float4 v0 = row[lane * 2], v1 = row[lane * 2 + 1];
        float4 a0 = xv[lane * 2], a1 = xv[lane * 2 + 1];
        float dp = v0.x*a0.x + v0.y*a0.y + v0.z*a0.z + v0.w*a0.w
                 + v1.x*a1.x + v1.y*a1.y + v1.z*a1.z + v1.w*a1.w;
        #pragma unroll
        for (int o = 16; o > 0; o >>= 1) dp += __shfl_xor_sync(0xffffffffu, dp, o);
        float s = g_nx2[gn] - 2.f * dp;
        unsigned long long k = ((unsigned long long)f2ord(s) << 32) | (unsigned)gn;
        if (k < key) key = k;
    }
    if (lane == 0) wmin[w] = key;
    __syncthreads();
    if (tid == 0) {
        unsigned long long best = wmin[0];
        #pragma unroll
        for (int i = 1; i < 8; i++) if (wmin[i] < best) best = wmin[i];
        g_min[q] = best;
    }
}

// ---------------------------------------------------------------------------
__global__ void finalize_kernel(const int* __restrict__ labels,
                                const int* __restrict__ tni,
                                const int* __restrict__ cali,
                                float* __restrict__ out,
                                int M, int ncali, int Kn) {
    __shared__ int scali[1024];
    __shared__ int wcnt[8][NBC];
    for (int i = threadIdx.x; i < ncali; i += blockDim.x) scali[i] = cali[i];
    int w = threadIdx.x >> 5, lane = threadIdx.x & 31;
    if (lane < NBC) wcnt[w][lane] = 0;
    __syncthreads();
    int b = blockIdx.x * 8 + w;
    if (b < M) {
        int closest = (int)(g_min[b] & 0xffffffffull);
        for (int e = lane; e < Kn; e += 32) {
            int idx = (e == 0) ? closest : tni[(size_t)closest * (Kn - 1) + (e - 1)];
            atomicAdd(&wcnt[w][labels[idx]], 1);
        }
        __syncwarp();
        int key = 0x7fffffff;
        if (lane < NBC) {
            int v = Kn - wcnt[w][lane];
            int lo = 0, hi = ncali;
            while (lo < hi) {
                int mid = (lo + hi) >> 1;
                if (scali[mid] < v) lo = mid + 1; else hi = mid;
            }
            key = lo * 16 + lane;
        }
        #pragma unroll
        for (int o = 16; o > 0; o >>= 1)
            key = min(key, __shfl_xor_sync(0xffffffffu, key, o));
        if (lane == 0) {
            int pred = key & 15, pos = key >> 4;
            float pmax = (float)(ncali - pos) / (float)ncali;
            #pragma unroll
            for (int c = 0; c < NBC; c++)
                out[b * NBC + c] = (c == pred) ? pmax : 0.f;
        }
    }
}

// ---------------------------------------------------------------------------
extern "C" void kernel_launch(void* const* d_in, const int* in_sizes, int n_in,
                              void* d_out, int out_size) {
    const float* x      = (const float*)d_in[0];
    const float* X      = (const float*)d_in[1];
    const float* center = (const float*)d_in[2];
    const int*   labels = (const int*)d_in[3];
    const int*   tni    = (const int*)d_in[4];
    const int*   cali   = (const int*)d_in[5];
    float*       out    = (float*)d_out;

    int d     = in_sizes[2];
    int M     = in_sizes[0] / d;
    int N     = in_sizes[3];
    int ncali = in_sizes[5];
    int Kn    = in_sizes[4] / N + 1;

    cudaFuncSetAttribute(gemm_kernel, cudaFuncAttributeMaxDynamicSharedMemorySize, SMEM_BYTES);

    prep_kernel<<<M, 256>>>(x, center, M);
    convert_kernel<<<(N + 7) / 8, 256>>>(X, N);
    init_kernel<<<(M + 255) / 256, 256>>>(M);

    dim3 grid((M + 127) / 128, (N + 127) / 128);
    gemm_kernel<<<grid, 256, SMEM_BYTES>>>(N, M);

    rescore_kernel<<<M, 256>>>(X);
    finalize_kernel<<<(M + 7) / 8, 256>>>(labels, tni, cali, out, M, ncali, Kn);
}